// round 6
// baseline (speedup 1.0000x reference)
#include <cuda_runtime.h>
#include <cstdint>

// yoloLoss: pred [B,7,7,30] f32, target [B,7,7,30] f32 -> out[3] f32
// Warp-specialized TMA pipeline, NO block-wide sync in the main loop:
//   warp 3  = producer: waits stage-empty, issues cp.async.bulk for next tile
//   warps 0-2 = consumers: wait stage-full (TMA tx barrier), each computes its
//               32 cells of the 96-cell tile, elected lane arrives on empty.
// Consumer warps are fully decoupled (per-warp stage cursors) and can skew.
// TILE=96 x 3 stages = 69KB dyn smem -> 3 blocks/SM, grid=444 (one wave).
// Balanced pair partition; last-done block does the deterministic
// double-precision final sum of block partials.

#define D 30
#define TPB 128
#define TILE 96                    // 3 consumer warps * 32 cells
#define STAGES 3
#define TILE_FLOATS (TILE * D)     // 2880 floats = 11520 B per tensor
#define STAGE_FLOATS (2 * TILE_FLOATS)               // 23040 B
#define DYN_SMEM_BYTES (STAGES * STAGE_FLOATS * 4)   // 69120
#define MAX_PART 4096

__device__ float g_partials[MAX_PART * 3];
__device__ unsigned int g_done = 0;

__device__ __forceinline__ float sq(float x) { return x * x; }

__device__ __forceinline__ uint32_t smem_u32(const void* p) {
    uint32_t a;
    asm("{ .reg .u64 t; cvta.to.shared.u64 t, %1; cvt.u32.u64 %0, t; }" : "=r"(a) : "l"(p));
    return a;
}
__device__ __forceinline__ void mbar_init(uint32_t mbar, uint32_t count) {
    asm volatile("mbarrier.init.shared.b64 [%0], %1;" :: "r"(mbar), "r"(count) : "memory");
}
__device__ __forceinline__ void mbar_expect_tx(uint32_t mbar, uint32_t bytes) {
    asm volatile("mbarrier.arrive.expect_tx.shared.b64 _, [%0], %1;" :: "r"(mbar), "r"(bytes) : "memory");
}
__device__ __forceinline__ void mbar_arrive(uint32_t mbar) {
    asm volatile("mbarrier.arrive.shared.b64 _, [%0];" :: "r"(mbar) : "memory");
}
__device__ __forceinline__ void mbar_wait_acq(uint32_t mbar, uint32_t parity) {
    uint32_t done;
    asm volatile(
        "{\n\t.reg .pred p;\n\t"
        "mbarrier.try_wait.parity.acquire.cta.shared::cta.b64 p, [%1], %2;\n\t"
        "selp.b32 %0, 1, 0, p;\n\t}"
        : "=r"(done) : "r"(mbar), "r"(parity) : "memory");
    if (!done) {
        asm volatile(
            "{\n\t.reg .pred P1;\n\t"
            "WL_%=:\n\t"
            "mbarrier.try_wait.parity.acquire.cta.shared::cta.b64 P1, [%0], %1, 0x989680;\n\t"
            "@P1 bra.uni WD_%=;\n\t"
            "bra.uni WL_%=;\n\t"
            "WD_%=:\n\t}"
            :: "r"(mbar), "r"(parity) : "memory");
    }
}
__device__ __forceinline__ void mbar_wait_rel(uint32_t mbar, uint32_t parity) {
    uint32_t done;
    asm volatile(
        "{\n\t.reg .pred p;\n\t"
        "mbarrier.try_wait.parity.relaxed.cta.shared::cta.b64 p, [%1], %2, 0x989680;\n\t"
        "selp.b32 %0, 1, 0, p;\n\t}"
        : "=r"(done) : "r"(mbar), "r"(parity) : "memory");
    if (!done) {
        asm volatile(
            "{\n\t.reg .pred P1;\n\t"
            "WL_%=:\n\t"
            "mbarrier.try_wait.parity.relaxed.cta.shared::cta.b64 P1, [%0], %1, 0x989680;\n\t"
            "@P1 bra.uni WD_%=;\n\t"
            "bra.uni WL_%=;\n\t"
            "WD_%=:\n\t}"
            :: "r"(mbar), "r"(parity) : "memory");
    }
}
__device__ __forceinline__ void bulk_g2s(uint32_t dst_smem, const void* src_gmem,
                                         uint32_t bytes, uint32_t mbar) {
    asm volatile(
        "cp.async.bulk.shared::cta.global.mbarrier::complete_tx::bytes [%0], [%1], %2, [%3];"
        :: "r"(dst_smem), "l"(src_gmem), "r"(bytes), "r"(mbar) : "memory");
}

__global__ void __launch_bounds__(TPB)
yolo_fused(const float* __restrict__ pred,
           const float* __restrict__ target,
           int pair_q, int pair_r, float inv_b,
           float* __restrict__ out)
{
    extern __shared__ float dyn[];                 // [STAGES][pred | targ]
    __shared__ unsigned long long full_s[STAGES];
    __shared__ unsigned long long empty_s[STAGES];
    __shared__ float red[TPB * 3];
    __shared__ bool is_last;

    const int tid = threadIdx.x;
    const int wid = tid >> 5;
    const int lane = tid & 31;
    const int b = blockIdx.x;
    const float STEPF = (float)(1.0 / 7.0);

    // Balanced partition in pair units (pair = 2 cells -> 240B-aligned bases).
    const int extra      = (b < pair_r) ? b : pair_r;
    const int start_cell = 2 * (b * pair_q + extra);
    const int ncell_blk  = 2 * (pair_q + (b < pair_r ? 1 : 0));
    const int ntiles     = (ncell_blk + TILE - 1) / TILE;

    uint32_t fullb[STAGES], emptyb[STAGES];
    #pragma unroll
    for (int s = 0; s < STAGES; ++s) {
        fullb[s]  = smem_u32(&full_s[s]);
        emptyb[s] = smem_u32(&empty_s[s]);
    }
    if (tid == 0) {
        #pragma unroll
        for (int s = 0; s < STAGES; ++s) {
            mbar_init(fullb[s], 1);    // flipped by TMA tx completion
            mbar_init(emptyb[s], 3);   // one arrive per consumer warp
        }
    }
    __syncthreads();

    float conf = 0.f, reg = 0.f, cls = 0.f;

    if (wid == 3) {
        // ---------------- producer warp ----------------
        if (lane == 0) {
            auto issue = [&](int tile_i, int s) {
                const int cells = min(TILE, ncell_blk - tile_i * TILE);
                const uint32_t bytes = (uint32_t)cells * D * 4u;   // cells even
                const long long gbase = (long long)(start_cell + tile_i * TILE) * D;
                const uint32_t sm_p = smem_u32(dyn + s * STAGE_FLOATS);
                const uint32_t sm_t = sm_p + TILE_FLOATS * 4u;
                mbar_expect_tx(fullb[s], 2u * bytes);
                bulk_g2s(sm_p, pred + gbase, bytes, fullb[s]);
                bulk_g2s(sm_t, target + gbase, bytes, fullb[s]);
            };
            const int pre = (ntiles < STAGES) ? ntiles : STAGES;
            for (int s = 0; s < pre; ++s) issue(s, s);
            int ph_e[STAGES] = {0, 0, 0};
            int s = 0;
            for (int i = STAGES; i < ntiles; ++i) {
                mbar_wait_rel(emptyb[s], ph_e[s]);   // consumers freed stage s
                ph_e[s] ^= 1;
                issue(i, s);
                s = (s + 1 == STAGES) ? 0 : s + 1;
            }
        }
    } else {
        // ---------------- consumer warps (0..2) ----------------
        int ph_f[STAGES] = {0, 0, 0};
        int s = 0;
        for (int i = 0; i < ntiles; ++i) {
            mbar_wait_acq(fullb[s], ph_f[s]);
            ph_f[s] ^= 1;

            const int cells = min(TILE, ncell_blk - i * TILE);
            const int cl = wid * 32 + lane;          // cell within tile
            if (cl < cells) {
                const float* p = dyn + s * STAGE_FLOATS + cl * D;
                const float* t = p + TILE_FLOATS;

                const int cell = start_cell + i * TILE + cl;
                const int ij = cell % 49;
                const float fi = (float)(ij / 7);
                const float fj = (float)(ij % 7);

                const float tv4 = t[4];
                const bool obj = (tv4 > 0.f);
                const bool noobj = (tv4 == 0.f);

                const float tw = t[2], th = t[3];
                const float a1 = fmaxf((t[0] + fj) * STEPF - tw * 0.5f, 0.f);
                const float b1 = fmaxf((t[1] + fi) * STEPF - th * 0.5f, 0.f);
                const float area_t = tw * th;

                auto iou_with = [&](float px, float py, float pw, float phh) -> float {
                    float a2 = fmaxf((px + fj) * STEPF - pw * 0.5f, 0.f);
                    float b2 = fmaxf((py + fi) * STEPF - phh * 0.5f, 0.f);
                    float iw = tw + pw - (fmaxf(a1 + tw, a2 + pw) - fminf(a1, a2));
                    float ih = th + phh - (fmaxf(b1 + th, b2 + phh) - fminf(b1, b2));
                    bool valid = (iw > 0.f) && (ih > 0.f);
                    float inter = valid ? iw * ih : 0.f;
                    float uni = area_t + pw * phh - inter;
                    return valid ? (inter / uni) : 0.f;
                };

                const float iou1 = iou_with(p[0], p[1], p[2], p[3]);
                const float iou2 = iou_with(p[5], p[6], p[7], p[8]);
                const bool choose1 = (iou1 > iou2);
                const float m1 = (obj && choose1 && (iou1 != 0.f)) ? 1.f : 0.f;
                const float m2 = (obj && !choose1 && (iou2 != 0.f)) ? 1.f : 0.f;

                float obj_l = m1 * sq(iou1 - p[4]) + m2 * sq(iou2 - p[9]);

                float xy = m1 * (sq(t[0] - p[0]) + sq(t[1] - p[1]))
                         + m2 * (sq(t[5] - p[5]) + sq(t[6] - p[6]));

                float wh = m1 * (sq(sqrtf(t[2]) - sqrtf(p[2])) + sq(sqrtf(t[3]) - sqrtf(p[3])))
                         + m2 * (sq(sqrtf(t[7]) - sqrtf(p[7])) + sq(sqrtf(t[8]) - sqrtf(p[8])));

                float nl = 0.f;
                #pragma unroll
                for (int k = 4; k < 30; k += 5) { float d = t[k] - p[k]; nl += d * d; }

                float cl2 = 0.f;
                #pragma unroll
                for (int k = 10; k < 30; ++k) { float d = p[k] - t[k]; cl2 += d * d; }

                conf += obj_l + 0.5f * (noobj ? nl : 0.f);
                reg  += 5.0f * (xy + wh);
                cls  += obj ? cl2 : 0.f;
            }
            __syncwarp();
            if (lane == 0) mbar_arrive(emptyb[s]);   // this warp done with stage s
            s = (s + 1 == STAGES) ? 0 : s + 1;
        }
    }

    // Block-level tree reduction (producer contributes zeros).
    red[tid]           = conf;
    red[TPB + tid]     = reg;
    red[2 * TPB + tid] = cls;
    __syncthreads();
    #pragma unroll
    for (int s = TPB / 2; s > 0; s >>= 1) {
        if (tid < s) {
            red[tid]           += red[tid + s];
            red[TPB + tid]     += red[TPB + tid + s];
            red[2 * TPB + tid] += red[2 * TPB + tid + s];
        }
        __syncthreads();
    }

    if (tid == 0) {
        g_partials[b * 3 + 0] = red[0];
        g_partials[b * 3 + 1] = red[TPB];
        g_partials[b * 3 + 2] = red[2 * TPB];
        __threadfence();
        unsigned int old = atomicAdd(&g_done, 1u);
        is_last = (old == gridDim.x - 1);
    }
    __syncthreads();

    if (is_last) {
        const int nblk = gridDim.x;
        double c = 0.0, r = 0.0, k = 0.0;
        for (int i = tid; i < nblk; i += TPB) {
            c += (double)g_partials[i * 3 + 0];
            r += (double)g_partials[i * 3 + 1];
            k += (double)g_partials[i * 3 + 2];
        }
        double* sd = (double*)dyn;       // reuse staging smem
        sd[tid]           = c;
        sd[TPB + tid]     = r;
        sd[2 * TPB + tid] = k;
        __syncthreads();
        #pragma unroll
        for (int s = TPB / 2; s > 0; s >>= 1) {
            if (tid < s) {
                sd[tid]           += sd[tid + s];
                sd[TPB + tid]     += sd[TPB + tid + s];
                sd[2 * TPB + tid] += sd[2 * TPB + tid + s];
            }
            __syncthreads();
        }
        if (tid == 0) {
            out[0] = (float)(sd[0]       * (double)inv_b);
            out[1] = (float)(sd[TPB]     * (double)inv_b);
            out[2] = (float)(sd[2 * TPB] * (double)inv_b);
            g_done = 0;                  // reset for next graph replay
        }
    }
}

extern "C" void kernel_launch(void* const* d_in, const int* in_sizes, int n_in,
                              void* d_out, int out_size)
{
    const float* pred   = (const float*)d_in[0];
    const float* target = (const float*)d_in[1];

    const int n_cells = in_sizes[0] / D;       // B*7*7 (even)
    const int n_pairs = n_cells / 2;

    int nblk = 148 * 3;                        // one wave at 69KB dyn smem/block
    if (nblk > n_pairs) nblk = n_pairs;
    if (nblk > MAX_PART) nblk = MAX_PART;

    const int pair_q = n_pairs / nblk;
    const int pair_r = n_pairs % nblk;
    const float inv_b = 49.0f / (float)n_cells;

    cudaFuncSetAttribute(yolo_fused, cudaFuncAttributeMaxDynamicSharedMemorySize,
                         DYN_SMEM_BYTES);
    yolo_fused<<<nblk, TPB, DYN_SMEM_BYTES>>>(pred, target, pair_q, pair_r, inv_b,
                                              (float*)d_out);
}

// round 7
// speedup vs baseline: 1.0467x; 1.0467x over previous
#include <cuda_runtime.h>
#include <cstdint>

// yoloLoss: pred [B,7,7,30] f32, target [B,7,7,30] f32 -> out[3] f32
// TMA double-buffered pipeline, 4 consumer warps + 1 dedicated producer warp
// (TPB=160). No block-wide sync in the main loop:
//   producer (warp 4, lane 0): waits stage-empty (4 consumer arrivals),
//                              issues cp.async.bulk pair for the next tile
//   consumers (warps 0-3): wait stage-full (TMA tx barrier), compute their 32
//                          cells via float2 smem loads, lane0 arrives empty.
// TILE=128 x 2 stages = 61.4KB dyn smem -> 3 blocks/SM, grid=444 (one wave).
// Balanced pair partition; last-done block does the deterministic
// double-precision final sum of block partials.

#define D 30
#define TPB 160                    // 4 consumer warps + 1 producer warp
#define NCONS 4
#define TILE 128                   // NCONS * 32 cells
#define STAGES 2
#define TILE_FLOATS (TILE * D)     // 3840 floats = 15360 B per tensor
#define STAGE_FLOATS (2 * TILE_FLOATS)               // 30720 B
#define DYN_SMEM_BYTES (STAGES * STAGE_FLOATS * 4)   // 61440
#define MAX_PART 4096

__device__ float g_partials[MAX_PART * 3];
__device__ unsigned int g_done = 0;

__device__ __forceinline__ float sq(float x) { return x * x; }

__device__ __forceinline__ uint32_t smem_u32(const void* p) {
    uint32_t a;
    asm("{ .reg .u64 t; cvta.to.shared.u64 t, %1; cvt.u32.u64 %0, t; }" : "=r"(a) : "l"(p));
    return a;
}
__device__ __forceinline__ void mbar_init(uint32_t mbar, uint32_t count) {
    asm volatile("mbarrier.init.shared.b64 [%0], %1;" :: "r"(mbar), "r"(count) : "memory");
}
__device__ __forceinline__ void mbar_expect_tx(uint32_t mbar, uint32_t bytes) {
    asm volatile("mbarrier.arrive.expect_tx.shared.b64 _, [%0], %1;" :: "r"(mbar), "r"(bytes) : "memory");
}
__device__ __forceinline__ void mbar_arrive(uint32_t mbar) {
    asm volatile("mbarrier.arrive.shared.b64 _, [%0];" :: "r"(mbar) : "memory");
}
__device__ __forceinline__ void mbar_wait_acq(uint32_t mbar, uint32_t parity) {
    uint32_t done;
    asm volatile(
        "{\n\t.reg .pred p;\n\t"
        "mbarrier.try_wait.parity.acquire.cta.shared::cta.b64 p, [%1], %2;\n\t"
        "selp.b32 %0, 1, 0, p;\n\t}"
        : "=r"(done) : "r"(mbar), "r"(parity) : "memory");
    if (!done) {
        asm volatile(
            "{\n\t.reg .pred P1;\n\t"
            "WL_%=:\n\t"
            "mbarrier.try_wait.parity.acquire.cta.shared::cta.b64 P1, [%0], %1, 0x989680;\n\t"
            "@P1 bra.uni WD_%=;\n\t"
            "bra.uni WL_%=;\n\t"
            "WD_%=:\n\t}"
            :: "r"(mbar), "r"(parity) : "memory");
    }
}
__device__ __forceinline__ void mbar_wait_rel(uint32_t mbar, uint32_t parity) {
    uint32_t done;
    asm volatile(
        "{\n\t.reg .pred p;\n\t"
        "mbarrier.try_wait.parity.relaxed.cta.shared::cta.b64 p, [%1], %2, 0x989680;\n\t"
        "selp.b32 %0, 1, 0, p;\n\t}"
        : "=r"(done) : "r"(mbar), "r"(parity) : "memory");
    if (!done) {
        asm volatile(
            "{\n\t.reg .pred P1;\n\t"
            "WL_%=:\n\t"
            "mbarrier.try_wait.parity.relaxed.cta.shared::cta.b64 P1, [%0], %1, 0x989680;\n\t"
            "@P1 bra.uni WD_%=;\n\t"
            "bra.uni WL_%=;\n\t"
            "WD_%=:\n\t}"
            :: "r"(mbar), "r"(parity) : "memory");
    }
}
__device__ __forceinline__ void bulk_g2s(uint32_t dst_smem, const void* src_gmem,
                                         uint32_t bytes, uint32_t mbar) {
    asm volatile(
        "cp.async.bulk.shared::cta.global.mbarrier::complete_tx::bytes [%0], [%1], %2, [%3];"
        :: "r"(dst_smem), "l"(src_gmem), "r"(bytes), "r"(mbar) : "memory");
}

__global__ void __launch_bounds__(TPB)
yolo_fused(const float* __restrict__ pred,
           const float* __restrict__ target,
           int pair_q, int pair_r, float inv_b,
           float* __restrict__ out)
{
    extern __shared__ float dyn[];                 // [STAGES][pred | targ]
    __shared__ unsigned long long full_s[STAGES];
    __shared__ unsigned long long empty_s[STAGES];
    __shared__ float wsum[5 * 3];                  // per-warp partials
    __shared__ double dsum[5 * 3];                 // epilogue warp partials
    __shared__ bool is_last;

    const int tid = threadIdx.x;
    const int wid = tid >> 5;
    const int lane = tid & 31;
    const int b = blockIdx.x;
    const float STEPF = (float)(1.0 / 7.0);

    // Balanced partition in pair units (pair = 2 cells -> 240B-aligned bases).
    const int extra      = (b < pair_r) ? b : pair_r;
    const int start_cell = 2 * (b * pair_q + extra);
    const int ncell_blk  = 2 * (pair_q + (b < pair_r ? 1 : 0));
    const int ntiles     = (ncell_blk + TILE - 1) / TILE;

    uint32_t fullb[STAGES], emptyb[STAGES];
    #pragma unroll
    for (int s = 0; s < STAGES; ++s) {
        fullb[s]  = smem_u32(&full_s[s]);
        emptyb[s] = smem_u32(&empty_s[s]);
    }
    if (tid == 0) {
        #pragma unroll
        for (int s = 0; s < STAGES; ++s) {
            mbar_init(fullb[s], 1);       // flipped by TMA tx completion
            mbar_init(emptyb[s], NCONS);  // one arrive per consumer warp
        }
    }
    __syncthreads();

    float conf = 0.f, reg = 0.f, cls = 0.f;

    if (wid == NCONS) {
        // ---------------- producer warp (no compute) ----------------
        if (lane == 0) {
            auto issue = [&](int tile_i, int s) {
                const int cells = min(TILE, ncell_blk - tile_i * TILE);
                const uint32_t bytes = (uint32_t)cells * D * 4u;   // cells even
                const long long gbase = (long long)(start_cell + tile_i * TILE) * D;
                const uint32_t sm_p = smem_u32(dyn + s * STAGE_FLOATS);
                const uint32_t sm_t = sm_p + TILE_FLOATS * 4u;
                mbar_expect_tx(fullb[s], 2u * bytes);
                bulk_g2s(sm_p, pred + gbase, bytes, fullb[s]);
                bulk_g2s(sm_t, target + gbase, bytes, fullb[s]);
            };
            const int pre = (ntiles < STAGES) ? ntiles : STAGES;
            for (int s = 0; s < pre; ++s) issue(s, s);
            int ph_e[STAGES] = {0, 0};
            int s = 0;
            for (int i = STAGES; i < ntiles; ++i) {
                mbar_wait_rel(emptyb[s], ph_e[s]);   // all consumers done with s
                ph_e[s] ^= 1;
                issue(i, s);
                s ^= 1;
            }
        }
    } else {
        // ---------------- consumer warps (0..3) ----------------
        int ph_f[STAGES] = {0, 0};
        int s = 0;
        for (int i = 0; i < ntiles; ++i) {
            mbar_wait_acq(fullb[s], ph_f[s]);
            ph_f[s] ^= 1;

            const int cells = min(TILE, ncell_blk - i * TILE);
            const int cl = wid * 32 + lane;          // cell within tile
            if (cl < cells) {
                // float2 views (cell base = 120B -> 8B aligned, conflict-free LDS.64)
                const float2* p2 = (const float2*)(dyn + s * STAGE_FLOATS + cl * D);
                const float2* t2 = (const float2*)(dyn + s * STAGE_FLOATS + TILE_FLOATS + cl * D);

                const int cell = start_cell + i * TILE + cl;
                const int ij = cell % 49;
                const float fi = (float)(ij / 7);
                const float fj = (float)(ij % 7);

                const float2 t01 = t2[0];   // t0 t1
                const float2 t23 = t2[1];   // t2 t3
                const float2 t45 = t2[2];   // t4 t5
                const float2 t67 = t2[3];   // t6 t7
                const float2 t89 = t2[4];   // t8 t9
                const float2 p01 = p2[0];
                const float2 p23 = p2[1];
                const float2 p45 = p2[2];
                const float2 p67 = p2[3];
                const float2 p89 = p2[4];

                const float tv4 = t45.x;
                const bool obj = (tv4 > 0.f);
                const bool noobj = (tv4 == 0.f);

                const float tw = t23.x, th = t23.y;
                const float a1 = fmaxf((t01.x + fj) * STEPF - tw * 0.5f, 0.f);
                const float b1 = fmaxf((t01.y + fi) * STEPF - th * 0.5f, 0.f);
                const float area_t = tw * th;

                auto iou_with = [&](float px, float py, float pw, float phh) -> float {
                    float a2 = fmaxf((px + fj) * STEPF - pw * 0.5f, 0.f);
                    float b2 = fmaxf((py + fi) * STEPF - phh * 0.5f, 0.f);
                    float iw = tw + pw - (fmaxf(a1 + tw, a2 + pw) - fminf(a1, a2));
                    float ih = th + phh - (fmaxf(b1 + th, b2 + phh) - fminf(b1, b2));
                    bool valid = (iw > 0.f) && (ih > 0.f);
                    float inter = valid ? iw * ih : 0.f;
                    float uni = area_t + pw * phh - inter;
                    return valid ? (inter / uni) : 0.f;
                };

                const float iou1 = iou_with(p01.x, p01.y, p23.x, p23.y);
                const float iou2 = iou_with(p45.y, p67.x, p67.y, p89.x);
                const bool choose1 = (iou1 > iou2);
                const float m1 = (obj && choose1 && (iou1 != 0.f)) ? 1.f : 0.f;
                const float m2 = (obj && !choose1 && (iou2 != 0.f)) ? 1.f : 0.f;

                float obj_l = m1 * sq(iou1 - p45.x) + m2 * sq(iou2 - p89.y);

                float xy = m1 * (sq(t01.x - p01.x) + sq(t01.y - p01.y))
                         + m2 * (sq(t45.y - p45.y) + sq(t67.x - p67.x));

                float wh = m1 * (sq(sqrtf(t23.x) - sqrtf(p23.x)) + sq(sqrtf(t23.y) - sqrtf(p23.y)))
                         + m2 * (sq(sqrtf(t67.y) - sqrtf(p67.y)) + sq(sqrtf(t89.x) - sqrtf(p89.x)));

                // class diffs k=10..29 (pairs 5..14); reuse k=14,19,24,29 for noobj
                float cl2 = 0.f;
                float d14 = 0.f, d19 = 0.f, d24 = 0.f, d29 = 0.f;
                #pragma unroll
                for (int k = 5; k < 15; ++k) {
                    float2 pv = p2[k];
                    float2 tv = t2[k];
                    float dx = pv.x - tv.x;
                    float dy = pv.y - tv.y;
                    float s2x = dx * dx, s2y = dy * dy;
                    cl2 += s2x + s2y;
                    if (k == 7)  d14 = s2x;   // index 14
                    if (k == 9)  d19 = s2y;   // index 19
                    if (k == 12) d24 = s2x;   // index 24
                    if (k == 14) d29 = s2y;   // index 29
                }
                float d4 = t45.x - p45.x;
                float d9 = t89.y - p89.y;
                float nl = d4 * d4 + d9 * d9 + d14 + d19 + d24 + d29;

                conf += obj_l + 0.5f * (noobj ? nl : 0.f);
                reg  += 5.0f * (xy + wh);
                cls  += obj ? cl2 : 0.f;
            }
            __syncwarp();
            if (lane == 0) mbar_arrive(emptyb[s]);   // this warp done with stage s
            s ^= 1;
        }
    }

    // Warp-level shuffle reduction, then tid0 combines 5 warp partials.
    #pragma unroll
    for (int o = 16; o > 0; o >>= 1) {
        conf += __shfl_down_sync(0xffffffffu, conf, o);
        reg  += __shfl_down_sync(0xffffffffu, reg,  o);
        cls  += __shfl_down_sync(0xffffffffu, cls,  o);
    }
    if (lane == 0) {
        wsum[wid * 3 + 0] = conf;
        wsum[wid * 3 + 1] = reg;
        wsum[wid * 3 + 2] = cls;
    }
    __syncthreads();

    if (tid == 0) {
        float c = 0.f, r = 0.f, k = 0.f;
        #pragma unroll
        for (int w = 0; w < 5; ++w) {
            c += wsum[w * 3 + 0];
            r += wsum[w * 3 + 1];
            k += wsum[w * 3 + 2];
        }
        g_partials[b * 3 + 0] = c;
        g_partials[b * 3 + 1] = r;
        g_partials[b * 3 + 2] = k;
        __threadfence();
        unsigned int old = atomicAdd(&g_done, 1u);
        is_last = (old == gridDim.x - 1);
    }
    __syncthreads();

    if (is_last) {
        const int nblk = gridDim.x;
        double c = 0.0, r = 0.0, k = 0.0;
        for (int i = tid; i < nblk; i += TPB) {
            c += (double)g_partials[i * 3 + 0];
            r += (double)g_partials[i * 3 + 1];
            k += (double)g_partials[i * 3 + 2];
        }
        #pragma unroll
        for (int o = 16; o > 0; o >>= 1) {
            c += __shfl_down_sync(0xffffffffu, c, o);
            r += __shfl_down_sync(0xffffffffu, r, o);
            k += __shfl_down_sync(0xffffffffu, k, o);
        }
        if (lane == 0) {
            dsum[wid * 3 + 0] = c;
            dsum[wid * 3 + 1] = r;
            dsum[wid * 3 + 2] = k;
        }
        __syncthreads();
        if (tid == 0) {
            double cc = 0.0, rr = 0.0, kk = 0.0;
            #pragma unroll
            for (int w = 0; w < 5; ++w) {
                cc += dsum[w * 3 + 0];
                rr += dsum[w * 3 + 1];
                kk += dsum[w * 3 + 2];
            }
            out[0] = (float)(cc * (double)inv_b);
            out[1] = (float)(rr * (double)inv_b);
            out[2] = (float)(kk * (double)inv_b);
            g_done = 0;   // reset for next graph replay
        }
    }
}

extern "C" void kernel_launch(void* const* d_in, const int* in_sizes, int n_in,
                              void* d_out, int out_size)
{
    const float* pred   = (const float*)d_in[0];
    const float* target = (const float*)d_in[1];

    const int n_cells = in_sizes[0] / D;       // B*7*7 (even)
    const int n_pairs = n_cells / 2;

    int nblk = 148 * 3;                        // one wave at 61.4KB dyn smem/block
    if (nblk > n_pairs) nblk = n_pairs;
    if (nblk > MAX_PART) nblk = MAX_PART;

    const int pair_q = n_pairs / nblk;
    const int pair_r = n_pairs % nblk;
    const float inv_b = 49.0f / (float)n_cells;

    cudaFuncSetAttribute(yolo_fused, cudaFuncAttributeMaxDynamicSharedMemorySize,
                         DYN_SMEM_BYTES);
    yolo_fused<<<nblk, TPB, DYN_SMEM_BYTES>>>(pred, target, pair_q, pair_r, inv_b,
                                              (float*)d_out);
}

// round 8
// speedup vs baseline: 1.1894x; 1.1364x over previous
#include <cuda_runtime.h>
#include <cstdint>

// yoloLoss: pred [B,7,7,30] f32, target [B,7,7,30] f32 -> out[3] f32
// TMA double-buffered pipeline at the smem occupancy ceiling:
//   TILE=224 cells, TPB=224 (7 warps, ALL consumers; tid0 issues TMA),
//   S=2 stages -> 107.5KB dyn smem/block -> 2 blocks/SM = 14 consumer
//   warps/SM (the 228KB smem ceiling), grid = 296 = one exact wave.
// Loop: wait stage-full (TMA tx mbarrier) -> compute -> __syncthreads ->
// tid0 issues tile i+2 into the freed stage.
// Balanced pair partition; warp-shuffle reductions; last-done block does the
// deterministic double-precision final sum of the 296 block partials.

#define D 30
#define TPB 224
#define TILE 224
#define STAGES 2
#define TILE_FLOATS (TILE * D)       // 6720 floats = 26880 B per tensor
#define STAGE_FLOATS (2 * TILE_FLOATS)               // 53760 B
#define DYN_SMEM_BYTES (STAGES * STAGE_FLOATS * 4)   // 107520
#define NWARP (TPB / 32)             // 7
#define MAX_PART 4096

__device__ float g_partials[MAX_PART * 3];
__device__ unsigned int g_done = 0;

__device__ __forceinline__ float sq(float x) { return x * x; }

__device__ __forceinline__ uint32_t smem_u32(const void* p) {
    uint32_t a;
    asm("{ .reg .u64 t; cvta.to.shared.u64 t, %1; cvt.u32.u64 %0, t; }" : "=r"(a) : "l"(p));
    return a;
}
__device__ __forceinline__ void mbar_init(uint32_t mbar, uint32_t count) {
    asm volatile("mbarrier.init.shared.b64 [%0], %1;" :: "r"(mbar), "r"(count) : "memory");
}
__device__ __forceinline__ void mbar_expect_tx(uint32_t mbar, uint32_t bytes) {
    asm volatile("mbarrier.arrive.expect_tx.shared.b64 _, [%0], %1;" :: "r"(mbar), "r"(bytes) : "memory");
}
__device__ __forceinline__ void mbar_wait_acq(uint32_t mbar, uint32_t parity) {
    uint32_t done;
    asm volatile(
        "{\n\t.reg .pred p;\n\t"
        "mbarrier.try_wait.parity.acquire.cta.shared::cta.b64 p, [%1], %2;\n\t"
        "selp.b32 %0, 1, 0, p;\n\t}"
        : "=r"(done) : "r"(mbar), "r"(parity) : "memory");
    if (!done) {
        asm volatile(
            "{\n\t.reg .pred P1;\n\t"
            "WL_%=:\n\t"
            "mbarrier.try_wait.parity.acquire.cta.shared::cta.b64 P1, [%0], %1, 0x989680;\n\t"
            "@P1 bra.uni WD_%=;\n\t"
            "bra.uni WL_%=;\n\t"
            "WD_%=:\n\t}"
            :: "r"(mbar), "r"(parity) : "memory");
    }
}
__device__ __forceinline__ void bulk_g2s(uint32_t dst_smem, const void* src_gmem,
                                         uint32_t bytes, uint32_t mbar) {
    asm volatile(
        "cp.async.bulk.shared::cta.global.mbarrier::complete_tx::bytes [%0], [%1], %2, [%3];"
        :: "r"(dst_smem), "l"(src_gmem), "r"(bytes), "r"(mbar) : "memory");
}

__global__ void __launch_bounds__(TPB)
yolo_fused(const float* __restrict__ pred,
           const float* __restrict__ target,
           int pair_q, int pair_r, float inv_b,
           float* __restrict__ out)
{
    extern __shared__ float dyn[];                 // [STAGES][pred | targ]
    __shared__ unsigned long long full_s[STAGES];
    __shared__ float wsum[NWARP * 3];
    __shared__ double dsum[NWARP * 3];
    __shared__ bool is_last;

    const int tid = threadIdx.x;
    const int wid = tid >> 5;
    const int lane = tid & 31;
    const int b = blockIdx.x;
    const float STEPF = (float)(1.0 / 7.0);

    // Balanced partition in pair units (pair = 2 cells -> 240B-aligned bases).
    const int extra      = (b < pair_r) ? b : pair_r;
    const int start_cell = 2 * (b * pair_q + extra);
    const int ncell_blk  = 2 * (pair_q + (b < pair_r ? 1 : 0));
    const int ntiles     = (ncell_blk + TILE - 1) / TILE;

    uint32_t fullb[STAGES];
    #pragma unroll
    for (int s = 0; s < STAGES; ++s) fullb[s] = smem_u32(&full_s[s]);

    if (tid == 0) {
        #pragma unroll
        for (int s = 0; s < STAGES; ++s) mbar_init(fullb[s], 1);
    }
    __syncthreads();

    auto issue = [&](int tile_i, int s) {
        const int cells = min(TILE, ncell_blk - tile_i * TILE);
        const uint32_t bytes = (uint32_t)cells * D * 4u;   // cells even -> mult of 16
        const long long gbase = (long long)(start_cell + tile_i * TILE) * D;
        const uint32_t sm_p = smem_u32(dyn + s * STAGE_FLOATS);
        const uint32_t sm_t = sm_p + TILE_FLOATS * 4u;
        mbar_expect_tx(fullb[s], 2u * bytes);
        bulk_g2s(sm_p, pred + gbase, bytes, fullb[s]);
        bulk_g2s(sm_t, target + gbase, bytes, fullb[s]);
    };

    if (tid == 0) {
        if (ntiles > 0) issue(0, 0);
        if (ntiles > 1) issue(1, 1);
    }

    float conf = 0.f, reg = 0.f, cls = 0.f;
    int ph[STAGES] = {0, 0};

    for (int i = 0; i < ntiles; ++i) {
        const int s = i & 1;
        mbar_wait_acq(fullb[s], ph[s]);
        ph[s] ^= 1;

        const int cells = min(TILE, ncell_blk - i * TILE);
        if (tid < cells) {
            // float2 views: cell base = tid*120B -> 8B aligned; lane stride
            // 15 8B-units mod 16 is a permutation -> optimal 2-way LDS.64.
            const float2* p2 = (const float2*)(dyn + s * STAGE_FLOATS + tid * D);
            const float2* t2 = (const float2*)(dyn + s * STAGE_FLOATS + TILE_FLOATS + tid * D);

            const int cell = start_cell + i * TILE + tid;
            const int ij = cell % 49;
            const float fi = (float)(ij / 7);
            const float fj = (float)(ij % 7);

            const float2 t01 = t2[0];
            const float2 t23 = t2[1];
            const float2 t45 = t2[2];
            const float2 t67 = t2[3];
            const float2 t89 = t2[4];
            const float2 p01 = p2[0];
            const float2 p23 = p2[1];
            const float2 p45 = p2[2];
            const float2 p67 = p2[3];
            const float2 p89 = p2[4];

            const float tv4 = t45.x;
            const bool obj = (tv4 > 0.f);
            const bool noobj = (tv4 == 0.f);

            const float tw = t23.x, th = t23.y;
            const float a1 = fmaxf((t01.x + fj) * STEPF - tw * 0.5f, 0.f);
            const float b1 = fmaxf((t01.y + fi) * STEPF - th * 0.5f, 0.f);
            const float area_t = tw * th;

            auto iou_with = [&](float px, float py, float pw, float phh) -> float {
                float a2 = fmaxf((px + fj) * STEPF - pw * 0.5f, 0.f);
                float b2 = fmaxf((py + fi) * STEPF - phh * 0.5f, 0.f);
                float iw = tw + pw - (fmaxf(a1 + tw, a2 + pw) - fminf(a1, a2));
                float ih = th + phh - (fmaxf(b1 + th, b2 + phh) - fminf(b1, b2));
                bool valid = (iw > 0.f) && (ih > 0.f);
                float inter = valid ? iw * ih : 0.f;
                float uni = area_t + pw * phh - inter;
                return valid ? (inter / uni) : 0.f;
            };

            const float iou1 = iou_with(p01.x, p01.y, p23.x, p23.y);
            const float iou2 = iou_with(p45.y, p67.x, p67.y, p89.x);
            const bool choose1 = (iou1 > iou2);
            const float m1 = (obj && choose1 && (iou1 != 0.f)) ? 1.f : 0.f;
            const float m2 = (obj && !choose1 && (iou2 != 0.f)) ? 1.f : 0.f;

            float obj_l = m1 * sq(iou1 - p45.x) + m2 * sq(iou2 - p89.y);

            float xy = m1 * (sq(t01.x - p01.x) + sq(t01.y - p01.y))
                     + m2 * (sq(t45.y - p45.y) + sq(t67.x - p67.x));

            float wh = m1 * (sq(sqrtf(t23.x) - sqrtf(p23.x)) + sq(sqrtf(t23.y) - sqrtf(p23.y)))
                     + m2 * (sq(sqrtf(t67.y) - sqrtf(p67.y)) + sq(sqrtf(t89.x) - sqrtf(p89.x)));

            // class diffs k=10..29 (float2 pairs 5..14); reuse k=14,19,24,29 for noobj
            float cl2 = 0.f;
            float d14 = 0.f, d19 = 0.f, d24 = 0.f, d29 = 0.f;
            #pragma unroll
            for (int k = 5; k < 15; ++k) {
                float2 pv = p2[k];
                float2 tv = t2[k];
                float dx = pv.x - tv.x;
                float dy = pv.y - tv.y;
                float s2x = dx * dx, s2y = dy * dy;
                cl2 += s2x + s2y;
                if (k == 7)  d14 = s2x;   // index 14
                if (k == 9)  d19 = s2y;   // index 19
                if (k == 12) d24 = s2x;   // index 24
                if (k == 14) d29 = s2y;   // index 29
            }
            float d4 = t45.x - p45.x;
            float d9 = t89.y - p89.y;
            float nl = d4 * d4 + d9 * d9 + d14 + d19 + d24 + d29;

            conf += obj_l + 0.5f * (noobj ? nl : 0.f);
            reg  += 5.0f * (xy + wh);
            cls  += obj ? cl2 : 0.f;
        }
        __syncthreads();                 // all warps done reading stage s
        if (tid == 0 && i + STAGES < ntiles) issue(i + STAGES, s);
    }

    // Warp shuffle reduction, then tid0 combines 7 warp partials.
    #pragma unroll
    for (int o = 16; o > 0; o >>= 1) {
        conf += __shfl_down_sync(0xffffffffu, conf, o);
        reg  += __shfl_down_sync(0xffffffffu, reg,  o);
        cls  += __shfl_down_sync(0xffffffffu, cls,  o);
    }
    if (lane == 0) {
        wsum[wid * 3 + 0] = conf;
        wsum[wid * 3 + 1] = reg;
        wsum[wid * 3 + 2] = cls;
    }
    __syncthreads();

    if (tid == 0) {
        float c = 0.f, r = 0.f, k = 0.f;
        #pragma unroll
        for (int w = 0; w < NWARP; ++w) {
            c += wsum[w * 3 + 0];
            r += wsum[w * 3 + 1];
            k += wsum[w * 3 + 2];
        }
        g_partials[b * 3 + 0] = c;
        g_partials[b * 3 + 1] = r;
        g_partials[b * 3 + 2] = k;
        __threadfence();
        unsigned int old = atomicAdd(&g_done, 1u);
        is_last = (old == gridDim.x - 1);
    }
    __syncthreads();

    if (is_last) {
        const int nblk = gridDim.x;
        double c = 0.0, r = 0.0, k = 0.0;
        for (int i = tid; i < nblk; i += TPB) {
            c += (double)g_partials[i * 3 + 0];
            r += (double)g_partials[i * 3 + 1];
            k += (double)g_partials[i * 3 + 2];
        }
        #pragma unroll
        for (int o = 16; o > 0; o >>= 1) {
            c += __shfl_down_sync(0xffffffffu, c, o);
            r += __shfl_down_sync(0xffffffffu, r, o);
            k += __shfl_down_sync(0xffffffffu, k, o);
        }
        if (lane == 0) {
            dsum[wid * 3 + 0] = c;
            dsum[wid * 3 + 1] = r;
            dsum[wid * 3 + 2] = k;
        }
        __syncthreads();
        if (tid == 0) {
            double cc = 0.0, rr = 0.0, kk = 0.0;
            #pragma unroll
            for (int w = 0; w < NWARP; ++w) {
                cc += dsum[w * 3 + 0];
                rr += dsum[w * 3 + 1];
                kk += dsum[w * 3 + 2];
            }
            out[0] = (float)(cc * (double)inv_b);
            out[1] = (float)(rr * (double)inv_b);
            out[2] = (float)(kk * (double)inv_b);
            g_done = 0;   // reset for next graph replay
        }
    }
}

extern "C" void kernel_launch(void* const* d_in, const int* in_sizes, int n_in,
                              void* d_out, int out_size)
{
    const float* pred   = (const float*)d_in[0];
    const float* target = (const float*)d_in[1];

    const int n_cells = in_sizes[0] / D;       // B*7*7 (even)
    const int n_pairs = n_cells / 2;

    int nblk = 148 * 2;                        // one wave at 107.5KB dyn smem/block
    if (nblk > n_pairs) nblk = n_pairs;
    if (nblk > MAX_PART) nblk = MAX_PART;

    const int pair_q = n_pairs / nblk;
    const int pair_r = n_pairs % nblk;
    const float inv_b = 49.0f / (float)n_cells;

    cudaFuncSetAttribute(yolo_fused, cudaFuncAttributeMaxDynamicSharedMemorySize,
                         DYN_SMEM_BYTES);
    yolo_fused<<<nblk, TPB, DYN_SMEM_BYTES>>>(pred, target, pair_q, pair_r, inv_b,
                                              (float*)d_out);
}